// round 9
// baseline (speedup 1.0000x reference)
#include <cuda_runtime.h>

#define NN 50000
#define NE 640000
#define NR 8
#define D1 128   // IN_DIM == HID_DIM
#define D2 64    // OUT_DIM

// Scratch (allocation-free rule: __device__ globals)
__device__ float g_rel1[(size_t)NR * NN * D1]; // 204.8 MB
__device__ float g_rel2[(size_t)NR * NN * D2]; // 102.4 MB
__device__ float g_h1[(size_t)NN * D1];        // 25.6 MB

// C[z] = (relu?)(A) @ W[z] (+ bias), A:[NN,128], W:[Z,128,DOUT], C:[Z,NN,DOUT]
template<int DOUT, bool RELU_IN, bool ADD_BIAS>
__global__ void __launch_bounds__(256) gemm_kernel(
    const float* __restrict__ A,
    const float* __restrict__ Wall,
    const float* __restrict__ bias,
    float* __restrict__ Call)
{
    constexpr int BM = 64, BK = 32;
    constexpr int TN = DOUT / 16;   // 8 (DOUT=128) or 4 (DOUT=64)
    constexpr int TM = 4;
    __shared__ float At[BM][BK];
    __shared__ float Wt[BK][DOUT];

    const float* W = Wall + (size_t)blockIdx.z * 128 * DOUT;
    float* C = Call + (size_t)blockIdx.z * NN * DOUT;

    const int tid = threadIdx.x;
    const int tx = tid & 15, ty = tid >> 4;
    const int rowBase = blockIdx.x * BM;

    float acc[TM][TN];
    #pragma unroll
    for (int i = 0; i < TM; i++)
        #pragma unroll
        for (int j = 0; j < TN; j++) acc[i][j] = 0.f;

    for (int k0 = 0; k0 < 128; k0 += BK) {
        // A tile: 64x32 = 512 float4, 2 per thread
        #pragma unroll
        for (int t = 0; t < 2; t++) {
            int idx = tid + t * 256;
            int r = idx >> 3;
            int kq = idx & 7;
            int grow = rowBase + r;
            float4 v = make_float4(0.f, 0.f, 0.f, 0.f);
            if (grow < NN)
                v = *(const float4*)(A + (size_t)grow * 128 + k0 + kq * 4);
            if (RELU_IN) {
                v.x = fmaxf(v.x, 0.f); v.y = fmaxf(v.y, 0.f);
                v.z = fmaxf(v.z, 0.f); v.w = fmaxf(v.w, 0.f);
            }
            *(float4*)(&At[r][kq * 4]) = v;
        }
        // W tile: BK x DOUT
        constexpr int WF4 = (BK * DOUT / 4) / 256;  // 4 or 2
        #pragma unroll
        for (int t = 0; t < WF4; t++) {
            int idx = tid + t * 256;
            int kk = idx / (DOUT / 4);
            int oq = idx % (DOUT / 4);
            float4 v = *(const float4*)(W + (size_t)(k0 + kk) * DOUT + oq * 4);
            *(float4*)(&Wt[kk][oq * 4]) = v;
        }
        __syncthreads();

        #pragma unroll
        for (int k = 0; k < BK; k++) {
            float a[TM];
            #pragma unroll
            for (int i = 0; i < TM; i++) a[i] = At[ty * TM + i][k];
            float w[TN];
            #pragma unroll
            for (int j = 0; j < TN; j += 4) {
                float4 wv = *(const float4*)(&Wt[k][tx * TN + j]);
                w[j] = wv.x; w[j + 1] = wv.y; w[j + 2] = wv.z; w[j + 3] = wv.w;
            }
            #pragma unroll
            for (int i = 0; i < TM; i++)
                #pragma unroll
                for (int j = 0; j < TN; j++)
                    acc[i][j] = fmaf(a[i], w[j], acc[i][j]);
        }
        __syncthreads();
    }

    #pragma unroll
    for (int i = 0; i < TM; i++) {
        int grow = rowBase + ty * TM + i;
        if (grow >= NN) continue;
        #pragma unroll
        for (int j = 0; j < TN; j += 4) {
            int col = tx * TN + j;
            float4 v = make_float4(acc[i][j], acc[i][j + 1], acc[i][j + 2], acc[i][j + 3]);
            if (ADD_BIAS) {
                v.x += bias[col];     v.y += bias[col + 1];
                v.z += bias[col + 2]; v.w += bias[col + 3];
            }
            *(float4*)(C + (size_t)grow * DOUT + col) = v;
        }
    }
}

// out[dst[e], :] += rel[et[e], src[e], :]
template<int DOUT>
__global__ void __launch_bounds__(256) scatter_kernel(
    const int* __restrict__ src,
    const int* __restrict__ dst,
    const int* __restrict__ et,
    const float* __restrict__ rel,
    float* __restrict__ out)
{
    constexpr int LPE = DOUT / 4;    // lanes per edge: 32 or 16
    constexpr int EPW = 32 / LPE;    // edges per warp:  1 or 2
    int warp = (blockIdx.x * blockDim.x + threadIdx.x) >> 5;
    int lane = threadIdx.x & 31;
    int e = warp * EPW + lane / LPE;
    if (e >= NE) return;
    int l = lane % LPE;
    int s = src[e], d = dst[e], r = et[e];
    float4 v = *(const float4*)(rel + ((size_t)r * NN + s) * DOUT + l * 4);
    float* o = out + (size_t)d * DOUT + l * 4;
    atomicAdd(o + 0, v.x);
    atomicAdd(o + 1, v.y);
    atomicAdd(o + 2, v.z);
    atomicAdd(o + 3, v.w);
}

extern "C" void kernel_launch(void* const* d_in, const int* in_sizes, int n_in,
                              void* d_out, int out_size)
{
    const float* feat = (const float*)d_in[0];
    const int*   src  = (const int*)d_in[1];
    const int*   dst  = (const int*)d_in[2];
    const int*   et   = (const int*)d_in[3];
    const float* W1   = (const float*)d_in[4];
    const float* W1s  = (const float*)d_in[5];
    const float* b1   = (const float*)d_in[6];
    const float* W2   = (const float*)d_in[7];
    const float* W2s  = (const float*)d_in[8];
    const float* b2   = (const float*)d_in[9];
    float* out = (float*)d_out;

    float *rel1, *rel2, *h1;
    cudaGetSymbolAddress((void**)&rel1, g_rel1);
    cudaGetSymbolAddress((void**)&rel2, g_rel2);
    cudaGetSymbolAddress((void**)&h1, g_h1);

    dim3 blk(256);
    int gm = (NN + 63) / 64;  // 782

    // Layer 1
    gemm_kernel<128, false, false><<<dim3(gm, 1, NR), blk>>>(feat, W1, nullptr, rel1);
    gemm_kernel<128, false, true ><<<dim3(gm, 1, 1 ), blk>>>(feat, W1s, b1, h1);
    scatter_kernel<128><<<(NE + 7) / 8, blk>>>(src, dst, et, rel1, h1);

    // Layer 2 (ReLU fused on reads of h1)
    gemm_kernel<64, true, false><<<dim3(gm, 1, NR), blk>>>(h1, W2, nullptr, rel2);
    gemm_kernel<64, true, true ><<<dim3(gm, 1, 1 ), blk>>>(h1, W2s, b2, out);
    scatter_kernel<64><<<(NE + 15) / 16, blk>>>(src, dst, et, rel2, out);
}

// round 10
// speedup vs baseline: 1.5114x; 1.5114x over previous
#include <cuda_runtime.h>

#define NN 50000
#define NE 640000
#define NR 8
#define D1 128
#define D2 64

// Scratch (allocation-free rule: __device__ globals)
__device__ float g_rel1[(size_t)NR * NN * D1]; // 204.8 MB
__device__ float g_rel2[(size_t)NR * NN * D2]; // 102.4 MB
__device__ float g_h1[(size_t)NN * D1];        // 25.6 MB
__device__ int   g_cnt[NN];
__device__ int   g_off[NN + 1];
__device__ int   g_cur[NN];
__device__ int   g_keys[NE];                   // et*NN + src, CSR-by-dst order

// ---------------- tf32 helpers ----------------
__device__ __forceinline__ unsigned f2tf32(float x) {
    unsigned r;
    asm("cvt.rna.tf32.f32 %0, %1;" : "=r"(r) : "f"(x));
    return r;
}

__device__ __forceinline__ void mma_tf32(float4& d, const unsigned a[4],
                                         unsigned b0, unsigned b1) {
    asm volatile(
        "mma.sync.aligned.m16n8k8.row.col.f32.tf32.tf32.f32 "
        "{%0,%1,%2,%3}, {%4,%5,%6,%7}, {%8,%9}, {%0,%1,%2,%3};\n"
        : "+f"(d.x), "+f"(d.y), "+f"(d.z), "+f"(d.w)
        : "r"(a[0]), "r"(a[1]), "r"(a[2]), "r"(a[3]), "r"(b0), "r"(b1));
}

// C[z] = (relu?)(A) @ W[z] (+ bias) with tf32x3 (hi*hi + hi*lo + lo*hi)
// A:[NN,128] fp32, W:[Z,128,DOUT], C:[Z,NN,DOUT]
template<int DOUT, bool RELU_IN, bool ADD_BIAS>
__global__ void __launch_bounds__(256) gemm_tf32(
    const float* __restrict__ A,
    const float* __restrict__ Wall,
    const float* __restrict__ bias,
    float* __restrict__ Call)
{
    constexpr int BM = 128, BK = 16;
    constexpr int AS = 20;         // padded A stride: (4*row+k)%32 bijective per warp
    constexpr int WS = DOUT + 8;   // padded W stride: (8k+n)%32 bijective per warp
    constexpr int NT = DOUT / 8;   // 16 or 8 n-tiles per warp

    __shared__ float As[BM][AS];
    __shared__ float Wh[BK][WS];
    __shared__ float Wl[BK][WS];

    const float* W = Wall + (size_t)blockIdx.z * 128 * DOUT;
    float* C = Call + (size_t)blockIdx.z * (size_t)NN * DOUT;

    const int tid  = threadIdx.x;
    const int warp = tid >> 5, lane = tid & 31;
    const int grp  = lane >> 2, tig = lane & 3;
    const int rowBase = blockIdx.x * BM;

    float4 acc[NT];
    #pragma unroll
    for (int nt = 0; nt < NT; nt++) acc[nt] = make_float4(0.f, 0.f, 0.f, 0.f);

    for (int k0 = 0; k0 < 128; k0 += BK) {
        // --- A tile: BM x BK = 512 float4, 2 per thread ---
        #pragma unroll
        for (int t = 0; t < 2; t++) {
            int idx = tid + t * 256;
            int r = idx >> 2, kq = idx & 3;
            int grow = rowBase + r;
            float4 v = make_float4(0.f, 0.f, 0.f, 0.f);
            if (grow < NN)
                v = *(const float4*)(A + (size_t)grow * 128 + k0 + kq * 4);
            if (RELU_IN) {
                v.x = fmaxf(v.x, 0.f); v.y = fmaxf(v.y, 0.f);
                v.z = fmaxf(v.z, 0.f); v.w = fmaxf(v.w, 0.f);
            }
            *(float4*)(&As[r][kq * 4]) = v;
        }
        // --- W tile: BK x DOUT, pre-split into tf32 hi/lo planes ---
        constexpr int WF = (BK * DOUT / 4) / 256;  // 2 (DOUT=128) or 1 (DOUT=64)
        #pragma unroll
        for (int t = 0; t < WF; t++) {
            int idx = tid + t * 256;
            int kk = idx / (DOUT / 4);
            int oq = idx % (DOUT / 4);
            float4 v = *(const float4*)(W + (size_t)(k0 + kk) * DOUT + oq * 4);
            float* wh = &Wh[kk][oq * 4];
            float* wl = &Wl[kk][oq * 4];
            float h;
            h = __uint_as_float(f2tf32(v.x)); wh[0] = h; wl[0] = __uint_as_float(f2tf32(v.x - h));
            h = __uint_as_float(f2tf32(v.y)); wh[1] = h; wl[1] = __uint_as_float(f2tf32(v.y - h));
            h = __uint_as_float(f2tf32(v.z)); wh[2] = h; wl[2] = __uint_as_float(f2tf32(v.z - h));
            h = __uint_as_float(f2tf32(v.w)); wh[3] = h; wl[3] = __uint_as_float(f2tf32(v.w - h));
        }
        __syncthreads();

        #pragma unroll
        for (int ks = 0; ks < BK; ks += 8) {
            const int r0 = warp * 16 + grp;
            float x0 = As[r0    ][ks + tig];
            float x1 = As[r0 + 8][ks + tig];
            float x2 = As[r0    ][ks + tig + 4];
            float x3 = As[r0 + 8][ks + tig + 4];
            unsigned ah[4], al[4];
            ah[0] = f2tf32(x0); al[0] = f2tf32(x0 - __uint_as_float(ah[0]));
            ah[1] = f2tf32(x1); al[1] = f2tf32(x1 - __uint_as_float(ah[1]));
            ah[2] = f2tf32(x2); al[2] = f2tf32(x2 - __uint_as_float(ah[2]));
            ah[3] = f2tf32(x3); al[3] = f2tf32(x3 - __uint_as_float(ah[3]));
            #pragma unroll
            for (int nt = 0; nt < NT; nt++) {
                const int n = nt * 8 + grp;
                unsigned bh0 = __float_as_uint(Wh[ks + tig    ][n]);
                unsigned bh1 = __float_as_uint(Wh[ks + tig + 4][n]);
                unsigned bl0 = __float_as_uint(Wl[ks + tig    ][n]);
                unsigned bl1 = __float_as_uint(Wl[ks + tig + 4][n]);
                mma_tf32(acc[nt], ah, bh0, bh1);
                mma_tf32(acc[nt], ah, bl0, bl1);
                mma_tf32(acc[nt], al, bh0, bh1);
            }
        }
        __syncthreads();
    }

    // --- epilogue: c0/c1 -> row r0, c2/c3 -> row r0+8, cols tig*2, tig*2+1 ---
    const int r0 = rowBase + warp * 16 + grp;
    #pragma unroll
    for (int nt = 0; nt < NT; nt++) {
        int col = nt * 8 + tig * 2;
        float2 v0 = make_float2(acc[nt].x, acc[nt].y);
        float2 v1 = make_float2(acc[nt].z, acc[nt].w);
        if (ADD_BIAS) {
            float b0v = bias[col], b1v = bias[col + 1];
            v0.x += b0v; v0.y += b1v;
            v1.x += b0v; v1.y += b1v;
        }
        if (r0 < NN)
            *(float2*)(C + (size_t)r0 * DOUT + col) = v0;
        if (r0 + 8 < NN)
            *(float2*)(C + (size_t)(r0 + 8) * DOUT + col) = v1;
    }
}

// ---------------- CSR build (by dst) ----------------
__global__ void __launch_bounds__(256) zero_cnt_kernel(int* __restrict__ cnt) {
    int i = blockIdx.x * 256 + threadIdx.x;
    if (i < NN) cnt[i] = 0;
}

__global__ void __launch_bounds__(256) hist_kernel(const int* __restrict__ dst,
                                                   int* __restrict__ cnt) {
    int e = blockIdx.x * 256 + threadIdx.x;
    if (e < NE) atomicAdd(&cnt[dst[e]], 1);
}

__global__ void __launch_bounds__(1024) scan_kernel(const int* __restrict__ cnt,
                                                    int* __restrict__ off,
                                                    int* __restrict__ cur) {
    __shared__ int part[1024];
    const int t = threadIdx.x;
    constexpr int C = (NN + 1023) / 1024;  // 49
    const int base = t * C;
    int s = 0;
    for (int i = 0; i < C; i++) {
        int idx = base + i;
        if (idx < NN) s += cnt[idx];
    }
    part[t] = s;
    __syncthreads();
    // Hillis-Steele inclusive scan
    for (int d = 1; d < 1024; d <<= 1) {
        int v = (t >= d) ? part[t - d] : 0;
        __syncthreads();
        part[t] += v;
        __syncthreads();
    }
    int run = (t == 0) ? 0 : part[t - 1];
    for (int i = 0; i < C; i++) {
        int idx = base + i;
        if (idx < NN) {
            off[idx] = run;
            cur[idx] = run;
            run += cnt[idx];
        }
    }
    if (t == 1023) off[NN] = run;  // == NE
}

__global__ void __launch_bounds__(256) fill_kernel(
    const int* __restrict__ src, const int* __restrict__ dst,
    const int* __restrict__ et, int* __restrict__ cur,
    int* __restrict__ keys)
{
    int e = blockIdx.x * 256 + threadIdx.x;
    if (e >= NE) return;
    int pos = atomicAdd(&cur[dst[e]], 1);
    keys[pos] = et[e] * NN + src[e];
}

// ---------------- atomic-free gather-aggregate ----------------
// out[d,:] += sum over incoming edges of rel[key(e), :]
template<int DOUT>
__global__ void __launch_bounds__(256) gather_kernel(
    const int* __restrict__ off, const int* __restrict__ keys,
    const float* __restrict__ rel, float* __restrict__ out)
{
    constexpr int LPN = DOUT / 4;   // lanes per node: 32 or 16
    constexpr int NPW = 32 / LPN;   // nodes per warp:  1 or 2
    int warp = (blockIdx.x * 256 + threadIdx.x) >> 5;
    int lane = threadIdx.x & 31;
    int d = warp * NPW + lane / LPN;
    if (d >= NN) return;
    int l = lane % LPN;
    int beg = off[d], end = off[d + 1];
    float4 acc = make_float4(0.f, 0.f, 0.f, 0.f);
    for (int j = beg; j < end; j++) {
        int key = keys[j];
        float4 v = *(const float4*)(rel + (size_t)key * DOUT + l * 4);
        acc.x += v.x; acc.y += v.y; acc.z += v.z; acc.w += v.w;
    }
    float* o = out + (size_t)d * DOUT + l * 4;
    float4 ov = *(float4*)o;
    ov.x += acc.x; ov.y += acc.y; ov.z += acc.z; ov.w += acc.w;
    *(float4*)o = ov;
}

extern "C" void kernel_launch(void* const* d_in, const int* in_sizes, int n_in,
                              void* d_out, int out_size)
{
    const float* feat = (const float*)d_in[0];
    const int*   src  = (const int*)d_in[1];
    const int*   dst  = (const int*)d_in[2];
    const int*   et   = (const int*)d_in[3];
    const float* W1   = (const float*)d_in[4];
    const float* W1s  = (const float*)d_in[5];
    const float* b1   = (const float*)d_in[6];
    const float* W2   = (const float*)d_in[7];
    const float* W2s  = (const float*)d_in[8];
    const float* b2   = (const float*)d_in[9];
    float* out = (float*)d_out;

    float *rel1, *rel2, *h1;
    int *cnt, *off, *cur, *keys;
    cudaGetSymbolAddress((void**)&rel1, g_rel1);
    cudaGetSymbolAddress((void**)&rel2, g_rel2);
    cudaGetSymbolAddress((void**)&h1,   g_h1);
    cudaGetSymbolAddress((void**)&cnt,  g_cnt);
    cudaGetSymbolAddress((void**)&off,  g_off);
    cudaGetSymbolAddress((void**)&cur,  g_cur);
    cudaGetSymbolAddress((void**)&keys, g_keys);

    dim3 blk(256);
    const int gm = (NN + 127) / 128;  // 391

    // CSR-by-dst build (shared by both layers)
    zero_cnt_kernel<<<(NN + 255) / 256, blk>>>(cnt);
    hist_kernel<<<(NE + 255) / 256, blk>>>(dst, cnt);
    scan_kernel<<<1, 1024>>>(cnt, off, cur);
    fill_kernel<<<(NE + 255) / 256, blk>>>(src, dst, et, cur, keys);

    // Layer 1
    gemm_tf32<128, false, false><<<dim3(gm, 1, NR), blk>>>(feat, W1,  nullptr, rel1);
    gemm_tf32<128, false, true ><<<dim3(gm, 1, 1 ), blk>>>(feat, W1s, b1,      h1);
    gather_kernel<128><<<(NN * 32 + 255) / 256, blk>>>(off, keys, rel1, h1);

    // Layer 2 (ReLU fused on reads of h1)
    gemm_tf32<64, true, false><<<dim3(gm, 1, NR), blk>>>(h1, W2,  nullptr, rel2);
    gemm_tf32<64, true, true ><<<dim3(gm, 1, 1 ), blk>>>(h1, W2s, b2,      out);
    gather_kernel<64><<<(NN * 16 + 255) / 256, blk>>>(off, keys, rel2, out);
}